// round 15
// baseline (speedup 1.0000x reference)
#include <cuda_runtime.h>
#include <cuda_bf16.h>
#include <cstdint>
#include <math.h>

#define B_  4
#define T_  2048
#define C_  768
#define NH_ 12
#define HD_ 64
#define RD_ 16
#define M_  (B_ * T_)          // 8192
#define NQKV (3 * C_)          // 2304
#define KB24 24                // 768 / 32

// ---------------- scratch ----------------------------------------------------
__device__ float g_qf[B_ * NH_ * T_ * HD_];      // Q frag order, tf32, scale*log2e folded
__device__ float g_kf[B_ * NH_ * T_ * HD_];      // K frag order, tf32
__device__ float g_vf[B_ * NH_ * T_ * HD_];      // V frag order, tf32
__device__ float g_of[M_ * C_];                  // attn out, A-fragment order, tf32
__device__ float g_xf[M_ * C_];                  // x, A-fragment order, tf32
__device__ float g_wqf[NQKV * C_];               // w_qkv, B-fragment order, tf32
__device__ float g_wof[C_ * C_];                 // w_out, B-fragment order, tf32

// ---------------- helpers -----------------------------------------------------
__device__ __forceinline__ float f2tf32(float x) {
    unsigned u;
    asm("cvt.rna.tf32.f32 %0, %1;" : "=r"(u) : "f"(x));
    return __uint_as_float(u);
}

__device__ __forceinline__ void mma_tf32(float* c,
    float a0, float a1, float a2, float a3, float b0, float b1)
{
    asm volatile(
        "mma.sync.aligned.m16n8k8.row.col.f32.tf32.tf32.f32 "
        "{%0,%1,%2,%3}, {%4,%5,%6,%7}, {%8,%9}, {%0,%1,%2,%3};"
        : "+f"(c[0]), "+f"(c[1]), "+f"(c[2]), "+f"(c[3])
        : "r"(__float_as_uint(a0)), "r"(__float_as_uint(a1)),
          "r"(__float_as_uint(a2)), "r"(__float_as_uint(a3)),
          "r"(__float_as_uint(b0)), "r"(__float_as_uint(b1)));
}

__device__ __forceinline__ void cp_async16(unsigned int smem_addr, const void* gptr) {
    asm volatile("cp.async.ca.shared.global [%0], [%1], 16;\n"
                 :: "r"(smem_addr), "l"(gptr));
}
__device__ __forceinline__ void cp_async_commit() {
    asm volatile("cp.async.commit_group;\n" ::: "memory");
}
__device__ __forceinline__ void cp_async_wait0() {
    asm volatile("cp.async.wait_group 0;\n" ::: "memory");
}
__device__ __forceinline__ void cp_async_wait1() {
    asm volatile("cp.async.wait_group 1;\n" ::: "memory");
}
__device__ __forceinline__ unsigned int smem_u32(const void* p) {
    return (unsigned int)__cvta_generic_to_shared(p);
}

// ---------------- prep: tf32-round + fragment reorder x / weights ---------------
__global__ __launch_bounds__(256) void prep_kernel(
    const float* __restrict__ x, const float* __restrict__ wq, const float* __restrict__ wo)
{
    int i = blockIdx.x * 256 + threadIdx.x;
    int stride = gridDim.x * 256;

    for (int j = i; j < M_ * C_; j += stride) {
        int m = j / C_, k = j - m * C_;
        float v = f2tf32(x[j]);
        int mblk = m >> 7, mi = m & 127;
        int wm = mi >> 6, mb = (mi >> 4) & 3, hi = (mi >> 3) & 1, ra = mi & 7;
        int it = k >> 5, kin = k & 31, ks = kin >> 3, c7 = kin & 7, half = c7 >> 2, cq = c7 & 3;
        size_t idx = (((size_t)(mblk * KB24 + it) * 8 + (wm * 4 + mb)) * 4 + ks) * 32 + (ra * 4 + cq);
        g_xf[idx * 4 + half * 2 + hi] = v;
    }
    for (int j = i; j < NQKV * C_; j += stride) {
        int n = j / C_, k = j - n * C_;
        float v = f2tf32(wq[j]);
        int nblk = n >> 7, ni = n & 127;
        int wn = ni >> 5, nb = (ni >> 3) & 3, ra = ni & 7;
        int p = nb >> 1, pb = nb & 1;
        int it = k >> 5, kin = k & 31, ks = kin >> 3, c7 = kin & 7, half = c7 >> 2, cq = c7 & 3;
        size_t idx = (((size_t)(nblk * KB24 + it) * 8 + (wn * 2 + p)) * 4 + ks) * 32 + (ra * 4 + cq);
        g_wqf[idx * 4 + pb * 2 + half] = v;
    }
    for (int j = i; j < C_ * C_; j += stride) {
        int n = j / C_, k = j - n * C_;
        float v = f2tf32(wo[j]);
        int nblk = n >> 7, ni = n & 127;
        int wn = ni >> 5, nb = (ni >> 3) & 3, ra = ni & 7;
        int p = nb >> 1, pb = nb & 1;
        int it = k >> 5, kin = k & 31, ks = kin >> 3, c7 = kin & 7, half = c7 >> 2, cq = c7 & 3;
        size_t idx = (((size_t)(nblk * KB24 + it) * 8 + (wn * 2 + p)) * 4 + ks) * 32 + (ra * 4 + cq);
        g_wof[idx * 4 + pb * 2 + half] = v;
    }
}

// ---------------- TF32 MMA GEMM: 4 warps, 64x64 warp tiles ---------------------
#define EPAD 132
#define GEMM_SMEM (3 * 2048 * 16)    // 98304 B

__global__ __launch_bounds__(128, 2) void gemm_tf32_kernel(
    const float4* __restrict__ Af, const float4* __restrict__ Bf,
    float* __restrict__ C, int KB, int N, int fuse_rope)
{
    extern __shared__ float4 sg4[];

    const int tid = threadIdx.x;
    const int warp = tid >> 5;           // 0..3
    const int lane = tid & 31;
    const int rA = lane >> 2;
    const int cq = lane & 3;
    const int warp_m = warp & 1;
    const int warp_n = warp >> 1;        // 0..1

    float acc[4][8][4];
#pragma unroll
    for (int a = 0; a < 4; a++)
#pragma unroll
        for (int b = 0; b < 8; b++)
#pragma unroll
            for (int c = 0; c < 4; c++) acc[a][b][c] = 0.f;

    auto issue = [&](int it, int st) {
        const float4* ga = Af + (size_t)(blockIdx.y * KB + it) * 1024;
        const float4* gb = Bf + (size_t)(blockIdx.x * KB + it) * 1024;
        float4* da = sg4 + st * 2048;
        float4* db = da + 1024;
#pragma unroll
        for (int l = 0; l < 8; l++) {
            int slot = l * 128 + tid;
            cp_async16(smem_u32(&da[slot]), &ga[slot]);
            cp_async16(smem_u32(&db[slot]), &gb[slot]);
        }
        cp_async_commit();
    };

    issue(0, 0);
    if (KB > 1) issue(1, 1);

    int st = 0, st2 = 2;
    for (int it = 0; it < KB; it++) {
        if (it + 1 < KB) cp_async_wait1(); else cp_async_wait0();
        __syncthreads();

        float4* As = sg4 + st * 2048;
        float4* Bs = As + 1024;
#pragma unroll
        for (int ks = 0; ks < 4; ks++) {
            float4 a4[4];
#pragma unroll
            for (int mb = 0; mb < 4; mb++)
                a4[mb] = As[((warp_m * 4 + mb) * 4 + ks) * 32 + lane];
            float4 b4[4];
#pragma unroll
            for (int g = 0; g < 4; g++)
                b4[g] = Bs[((warp_n * 4 + g) * 4 + ks) * 32 + lane];
#pragma unroll
            for (int mb = 0; mb < 4; mb++)
#pragma unroll
                for (int g = 0; g < 4; g++) {
                    mma_tf32(acc[mb][2 * g],     a4[mb].x, a4[mb].y, a4[mb].z, a4[mb].w, b4[g].x, b4[g].y);
                    mma_tf32(acc[mb][2 * g + 1], a4[mb].x, a4[mb].y, a4[mb].z, a4[mb].w, b4[g].z, b4[g].w);
                }
        }

        if (it + 2 < KB) issue(it + 2, st2);
        st = (st == 2) ? 0 : st + 1;
        st2 = (st2 == 2) ? 0 : st2 + 1;
    }

    const int m0 = blockIdx.y * 128;
    const int n0 = blockIdx.x * 128;

    if (!fuse_rope) {
#pragma unroll
        for (int mb = 0; mb < 4; mb++) {
            int row = m0 + warp_m * 64 + mb * 16 + rA;
#pragma unroll
            for (int nbb = 0; nbb < 8; nbb++) {
                int col = n0 + warp_n * 64 + nbb * 8 + 2 * cq;
                *(float2*)&C[(size_t)row * N + col] =
                    make_float2(acc[mb][nbb][0], acc[mb][nbb][1]);
                *(float2*)&C[(size_t)(row + 8) * N + col] =
                    make_float2(acc[mb][nbb][2], acc[mb][nbb][3]);
            }
        }
        return;
    }

    // --- fused RoPE + fragment scatter epilogue (QKV GEMM only) ---
    __syncthreads();
    float* ep = (float*)sg4;             // overlay [128][132]
#pragma unroll
    for (int mb = 0; mb < 4; mb++) {
        int row = warp_m * 64 + mb * 16 + rA;
#pragma unroll
        for (int nbb = 0; nbb < 8; nbb++) {
            int col = warp_n * 64 + nbb * 8 + 2 * cq;
            *(float2*)&ep[row * EPAD + col] = make_float2(acc[mb][nbb][0], acc[mb][nbb][1]);
            *(float2*)&ep[(row + 8) * EPAD + col] = make_float2(acc[mb][nbb][2], acc[mb][nbb][3]);
        }
    }
    __syncthreads();

    const int sel = n0 / C_;
    const int cbase = n0 % C_;

#pragma unroll 4
    for (int e = 0; e < 128; e++) {
        int elem = e * 128 + tid;
        int r = elem >> 7, c = elem & 127;
        float val = ep[r * EPAD + c];

        int cc = cbase + c;
        int h = cc >> 6, d = cc & 63;
        int m = m0 + r;
        int b = m >> 11, t = m & (T_ - 1);

        if (sel < 2 && d < RD_) {
            int j = (d < 8) ? d : d - 8;
            float freq = __powf(10000.0f, -(float)j / 8.0f);
            float ang = (float)t * freq;
            float cs = cosf(ang), sn = sinf(ang);
            float partner = ep[r * EPAD + ((d < 8) ? c + 8 : c - 8)];
            val = (d < 8) ? (val * cs - partner * sn) : (val * cs + partner * sn);
        }
        if (sel == 0) val *= 0.125f * 1.4426950408889634f;
        val = f2tf32(val);

        const int bh = b * NH_ + h;
        if (sel == 0) {
            int g = t >> 4, tl = t & 15;
            int hi = tl >> 3, ra = tl & 7;
            int kb = d >> 3, c7 = d & 7, reg = c7 >> 2, q4 = c7 & 3;
            size_t off = (((size_t)bh * 128 + g) * 8 + kb) * 128 + (ra * 4 + q4) * 4 + hi + 2 * reg;
            g_qf[off] = val;
        } else if (sel == 1) {
            int kt = t >> 6, tl = t & 63;
            int nb = tl >> 3, ra = tl & 7;
            int kb = d >> 3, c7 = d & 7, reg = c7 >> 2, q4 = c7 & 3;
            size_t off = ((size_t)bh * 32 + kt) * 4096
                       + ((nb * 4 + (kb >> 1)) * 32 + ra * 4 + q4) * 4 + (kb & 1) * 2 + reg;
            g_kf[off] = val;
        } else {
            int kt = t >> 6, tl = t & 63;
            int kb2 = tl >> 3, c7 = tl & 7, reg = c7 >> 2, q4 = c7 & 3;
            int nb2 = d >> 3, ra = d & 7;
            size_t off = ((size_t)bh * 32 + kt) * 4096
                       + ((kb2 * 4 + (nb2 >> 1)) * 32 + ra * 4 + q4) * 4 + (nb2 & 1) * 2 + reg;
            g_vf[off] = val;
        }
    }
}

// ---------------- Flash attention: 4 warps x 32 q-rows, 3-stage pipeline -------
#define FLASH_SMEM (6 * 1024 * 16)   // 98304 B

__global__ __launch_bounds__(128, 2) void flash_kernel()
{
    extern __shared__ float4 smf[];

    const int tid = threadIdx.x;
    const int warp = tid >> 5;           // 0..3
    const int lane = tid & 31;
    const int rA = lane >> 2;
    const int cq = lane & 3;

    const int qt = (int)gridDim.x - 1 - (int)blockIdx.x;
    const int bh = blockIdx.y;
    const int q0 = qt * 128;

    const int b = bh / NH_, h = bh % NH_;
    int qrow[2];
    qrow[0] = q0 + warp * 32 + rA;
    qrow[1] = qrow[0] + 16;

    const float4* Qf = (const float4*)g_qf;
    float qa[2][8][4];
#pragma unroll
    for (int mh = 0; mh < 2; mh++)
#pragma unroll
        for (int kb = 0; kb < 8; kb++) {
            float4 f = Qf[(((size_t)bh * 128 + 8 * qt + 2 * warp + mh) * 8 + kb) * 32 + lane];
            qa[mh][kb][0] = f.x; qa[mh][kb][1] = f.y; qa[mh][kb][2] = f.z; qa[mh][kb][3] = f.w;
        }

    float o[2][8][4];
#pragma unroll
    for (int mh = 0; mh < 2; mh++)
#pragma unroll
        for (int i = 0; i < 8; i++)
#pragma unroll
            for (int j = 0; j < 4; j++) o[mh][i][j] = 0.f;
    float mA[2] = {-1e30f, -1e30f}, mB[2] = {-1e30f, -1e30f};
    float lA[2] = {0.f, 0.f}, lB[2] = {0.f, 0.f};

    const float4* Kf = (const float4*)g_kf;
    const float4* Vf = (const float4*)g_vf;

    auto issue_tile = [&](int kt, int st) {
        const size_t tb = ((size_t)bh * 32 + kt) * 1024;
        float4* Ksb = smf + st * 1024;
        float4* Vsb = smf + 3072 + st * 1024;
#pragma unroll
        for (int l = 0; l < 8; l++) {
            int slot = l * 128 + tid;
            cp_async16(smem_u32(&Ksb[slot]), &Kf[tb + slot]);
            cp_async16(smem_u32(&Vsb[slot]), &Vf[tb + slot]);
        }
        cp_async_commit();
    };

    const int ktiles = 2 * qt + 2;
    issue_tile(0, 0);
    if (ktiles > 1) issue_tile(1, 1);

    const int srcA = (lane & ~3) | (cq >> 1);
    const int srcB = srcA + 2;
    const bool par = (cq & 1);

    int st = 0, st2 = 2;
    for (int kt = 0; kt < ktiles; kt++) {
        if (kt + 1 < ktiles) cp_async_wait1(); else cp_async_wait0();
        __syncthreads();

        float4* Ksf = smf + st * 1024;
        float4* Vsf = smf + 3072 + st * 1024;

        float s[2][8][4];
#pragma unroll
        for (int mh = 0; mh < 2; mh++)
#pragma unroll
            for (int nb = 0; nb < 8; nb++)
#pragma unroll
                for (int j = 0; j < 4; j++) s[mh][nb][j] = 0.f;
#pragma unroll
        for (int kbp = 0; kbp < 4; kbp++) {
#pragma unroll
            for (int nb = 0; nb < 8; nb++) {
                float4 f = Ksf[(nb * 4 + kbp) * 32 + lane];
#pragma unroll
                for (int mh = 0; mh < 2; mh++) {
                    mma_tf32(s[mh][nb], qa[mh][2 * kbp][0], qa[mh][2 * kbp][1],
                             qa[mh][2 * kbp][2], qa[mh][2 * kbp][3], f.x, f.y);
                    mma_tf32(s[mh][nb], qa[mh][2 * kbp + 1][0], qa[mh][2 * kbp + 1][1],
                             qa[mh][2 * kbp + 1][2], qa[mh][2 * kbp + 1][3], f.z, f.w);
                }
            }
        }

        const int k0 = kt * 64;
#pragma unroll
        for (int mh = 0; mh < 2; mh++) {
            if (k0 + 63 > qrow[mh]) {
#pragma unroll
                for (int nb = 0; nb < 8; nb++) {
                    int col = k0 + 8 * nb + 2 * cq;
                    if (col > qrow[mh])     s[mh][nb][0] = -1e30f;
                    if (col + 1 > qrow[mh]) s[mh][nb][1] = -1e30f;
                    if (col > qrow[mh] + 8)     s[mh][nb][2] = -1e30f;
                    if (col + 1 > qrow[mh] + 8) s[mh][nb][3] = -1e30f;
                }
            }

            float rmaxA = -1e30f, rmaxB = -1e30f;
#pragma unroll
            for (int nb = 0; nb < 8; nb++) {
                rmaxA = fmaxf(rmaxA, fmaxf(s[mh][nb][0], s[mh][nb][1]));
                rmaxB = fmaxf(rmaxB, fmaxf(s[mh][nb][2], s[mh][nb][3]));
            }
            rmaxA = fmaxf(rmaxA, __shfl_xor_sync(0xffffffffu, rmaxA, 1));
            rmaxA = fmaxf(rmaxA, __shfl_xor_sync(0xffffffffu, rmaxA, 2));
            rmaxB = fmaxf(rmaxB, __shfl_xor_sync(0xffffffffu, rmaxB, 1));
            rmaxB = fmaxf(rmaxB, __shfl_xor_sync(0xffffffffu, rmaxB, 2));

            float mnA = fmaxf(mA[mh], rmaxA), mnB = fmaxf(mB[mh], rmaxB);
            float alA = exp2f(mA[mh] - mnA), alB = exp2f(mB[mh] - mnB);
            mA[mh] = mnA; mB[mh] = mnB;

            float sumA = 0.f, sumB = 0.f;
#pragma unroll
            for (int nb = 0; nb < 8; nb++) {
                s[mh][nb][0] = exp2f(s[mh][nb][0] - mnA); sumA += s[mh][nb][0];
                s[mh][nb][1] = exp2f(s[mh][nb][1] - mnA); sumA += s[mh][nb][1];
                s[mh][nb][2] = exp2f(s[mh][nb][2] - mnB); sumB += s[mh][nb][2];
                s[mh][nb][3] = exp2f(s[mh][nb][3] - mnB); sumB += s[mh][nb][3];
            }
            sumA += __shfl_xor_sync(0xffffffffu, sumA, 1);
            sumA += __shfl_xor_sync(0xffffffffu, sumA, 2);
            sumB += __shfl_xor_sync(0xffffffffu, sumB, 1);
            sumB += __shfl_xor_sync(0xffffffffu, sumB, 2);
            lA[mh] = lA[mh] * alA + sumA;
            lB[mh] = lB[mh] * alB + sumB;

#pragma unroll
            for (int nb = 0; nb < 8; nb++) {
                o[mh][nb][0] *= alA; o[mh][nb][1] *= alA;
                o[mh][nb][2] *= alB; o[mh][nb][3] *= alB;
            }

#pragma unroll
            for (int nb = 0; nb < 8; nb++)
#pragma unroll
                for (int j = 0; j < 4; j++) s[mh][nb][j] = f2tf32(s[mh][nb][j]);
        }

        // O += P V
#pragma unroll
        for (int kb2 = 0; kb2 < 8; kb2++) {
            float pa[2][4];
#pragma unroll
            for (int mh = 0; mh < 2; mh++) {
                float t0, t1;
                t0 = __shfl_sync(0xffffffffu, s[mh][kb2][0], srcA);
                t1 = __shfl_sync(0xffffffffu, s[mh][kb2][1], srcA);
                pa[mh][0] = par ? t1 : t0;
                t0 = __shfl_sync(0xffffffffu, s[mh][kb2][0], srcB);
                t1 = __shfl_sync(0xffffffffu, s[mh][kb2][1], srcB);
                pa[mh][2] = par ? t1 : t0;
                t0 = __shfl_sync(0xffffffffu, s[mh][kb2][2], srcA);
                t1 = __shfl_sync(0xffffffffu, s[mh][kb2][3], srcA);
                pa[mh][1] = par ? t1 : t0;
                t0 = __shfl_sync(0xffffffffu, s[mh][kb2][2], srcB);
                t1 = __shfl_sync(0xffffffffu, s[mh][kb2][3], srcB);
                pa[mh][3] = par ? t1 : t0;
            }
#pragma unroll
            for (int nb2p = 0; nb2p < 4; nb2p++) {
                float4 f = Vsf[(kb2 * 4 + nb2p) * 32 + lane];
#pragma unroll
                for (int mh = 0; mh < 2; mh++) {
                    mma_tf32(o[mh][2 * nb2p],     pa[mh][0], pa[mh][1], pa[mh][2], pa[mh][3], f.x, f.y);
                    mma_tf32(o[mh][2 * nb2p + 1], pa[mh][0], pa[mh][1], pa[mh][2], pa[mh][3], f.z, f.w);
                }
            }
        }

        if (kt + 2 < ktiles) issue_tile(kt + 2, st2);
        st = (st == 2) ? 0 : st + 1;
        st2 = (st2 == 2) ? 0 : st2 + 1;
    }

    // epilogue: normalize, tf32-round, C->A layout shuffle, store A-fragment order
    float4* Of4 = (float4*)g_of;
#pragma unroll
    for (int mh = 0; mh < 2; mh++) {
        float invA = 1.f / lA[mh], invB = 1.f / lB[mh];
#pragma unroll
        for (int nb2 = 0; nb2 < 8; nb2++) {
            float s0 = f2tf32(o[mh][nb2][0] * invA);
            float s1 = f2tf32(o[mh][nb2][1] * invA);
            float s2 = f2tf32(o[mh][nb2][2] * invB);
            float s3 = f2tf32(o[mh][nb2][3] * invB);

            float t0, t1;
            t0 = __shfl_sync(0xffffffffu, s0, srcA);
            t1 = __shfl_sync(0xffffffffu, s1, srcA);
            float pa0 = par ? t1 : t0;
            t0 = __shfl_sync(0xffffffffu, s0, srcB);
            t1 = __shfl_sync(0xffffffffu, s1, srcB);
            float pa2 = par ? t1 : t0;
            t0 = __shfl_sync(0xffffffffu, s2, srcA);
            t1 = __shfl_sync(0xffffffffu, s3, srcA);
            float pa1 = par ? t1 : t0;
            t0 = __shfl_sync(0xffffffffu, s2, srcB);
            t1 = __shfl_sync(0xffffffffu, s3, srcB);
            float pa3 = par ? t1 : t0;

            int itl = nb2 >> 2, ks = nb2 & 3;
            size_t idx = (((size_t)((b * 16 + qt) * KB24 + (2 * h + itl)) * 8 + (2 * warp + mh)) * 4 + ks) * 32 + lane;
            Of4[idx] = make_float4(pa0, pa1, pa2, pa3);
        }
    }
}

// ---------------- launch ------------------------------------------------------
extern "C" void kernel_launch(void* const* d_in, const int* in_sizes, int n_in,
                              void* d_out, int out_size)
{
    const float* x     = (const float*)d_in[0];
    const float* w_qkv = (const float*)d_in[1];
    const float* w_out = (const float*)d_in[2];
    float* out = (float*)d_out;

    float *xf_p, *of_p, *wqf_p, *wof_p;
    cudaGetSymbolAddress((void**)&xf_p, g_xf);
    cudaGetSymbolAddress((void**)&of_p, g_of);
    cudaGetSymbolAddress((void**)&wqf_p, g_wqf);
    cudaGetSymbolAddress((void**)&wof_p, g_wof);

    // 0) round + fragment-reorder inputs
    prep_kernel<<<2048, 256>>>(x, w_qkv, w_out);

    cudaFuncSetAttribute(gemm_tf32_kernel, cudaFuncAttributeMaxDynamicSharedMemorySize, GEMM_SMEM);
    cudaFuncSetAttribute(flash_kernel, cudaFuncAttributeMaxDynamicSharedMemorySize, FLASH_SMEM);

    // 1) QKV GEMM with fused RoPE + fragment scatter
    {
        dim3 grid(NQKV / 128, M_ / 128);
        gemm_tf32_kernel<<<grid, 128, GEMM_SMEM>>>(
            (const float4*)xf_p, (const float4*)wqf_p, nullptr, KB24, NQKV, 1);
    }

    // 2) flash attention (writes g_of in A-fragment order)
    {
        dim3 grid(T_ / 128, B_ * NH_);
        flash_kernel<<<grid, 128, FLASH_SMEM>>>();
    }

    // 3) out projection (plain epilogue, row-major final output)
    {
        dim3 grid(C_ / 128, M_ / 128);
        gemm_tf32_kernel<<<grid, 128, GEMM_SMEM>>>(
            (const float4*)of_p, (const float4*)wof_p, out, KB24, C_, 0);
    }
}

// round 16
// speedup vs baseline: 1.0282x; 1.0282x over previous
#include <cuda_runtime.h>
#include <cuda_bf16.h>
#include <cstdint>
#include <math.h>

#define B_  4
#define T_  2048
#define C_  768
#define NH_ 12
#define HD_ 64
#define RD_ 16
#define M_  (B_ * T_)          // 8192
#define NQKV (3 * C_)          // 2304
#define KB24 24                // 768 / 32

// ---------------- scratch ----------------------------------------------------
__device__ float g_qf[B_ * NH_ * T_ * HD_];      // Q frag order, tf32, scale*log2e folded
__device__ float g_kf[B_ * NH_ * T_ * HD_];      // K frag order, tf32
__device__ float g_vf[B_ * NH_ * T_ * HD_];      // V frag order, tf32
__device__ float g_of[M_ * C_];                  // attn out, A-fragment order, tf32
__device__ float g_xf[M_ * C_];                  // x, A-fragment order, tf32
__device__ float g_wqf[NQKV * C_];               // w_qkv, B-fragment order, tf32
__device__ float g_wof[C_ * C_];                 // w_out, B-fragment order, tf32

// ---------------- helpers -----------------------------------------------------
__device__ __forceinline__ float f2tf32(float x) {
    unsigned u;
    asm("cvt.rna.tf32.f32 %0, %1;" : "=r"(u) : "f"(x));
    return __uint_as_float(u);
}

__device__ __forceinline__ void mma_tf32(float* c,
    float a0, float a1, float a2, float a3, float b0, float b1)
{
    asm volatile(
        "mma.sync.aligned.m16n8k8.row.col.f32.tf32.tf32.f32 "
        "{%0,%1,%2,%3}, {%4,%5,%6,%7}, {%8,%9}, {%0,%1,%2,%3};"
        : "+f"(c[0]), "+f"(c[1]), "+f"(c[2]), "+f"(c[3])
        : "r"(__float_as_uint(a0)), "r"(__float_as_uint(a1)),
          "r"(__float_as_uint(a2)), "r"(__float_as_uint(a3)),
          "r"(__float_as_uint(b0)), "r"(__float_as_uint(b1)));
}

__device__ __forceinline__ void cp_async16(unsigned int smem_addr, const void* gptr) {
    asm volatile("cp.async.ca.shared.global [%0], [%1], 16;\n"
                 :: "r"(smem_addr), "l"(gptr));
}
__device__ __forceinline__ void cp_async_commit() {
    asm volatile("cp.async.commit_group;\n" ::: "memory");
}
__device__ __forceinline__ void cp_async_wait0() {
    asm volatile("cp.async.wait_group 0;\n" ::: "memory");
}
__device__ __forceinline__ void cp_async_wait1() {
    asm volatile("cp.async.wait_group 1;\n" ::: "memory");
}
__device__ __forceinline__ unsigned int smem_u32(const void* p) {
    return (unsigned int)__cvta_generic_to_shared(p);
}

// ---------------- prep: tf32-round + fragment reorder x / weights ---------------
__global__ __launch_bounds__(256) void prep_kernel(
    const float* __restrict__ x, const float* __restrict__ wq, const float* __restrict__ wo)
{
    int i = blockIdx.x * 256 + threadIdx.x;
    int stride = gridDim.x * 256;

    for (int j = i; j < M_ * C_; j += stride) {
        int m = j / C_, k = j - m * C_;
        float v = f2tf32(x[j]);
        int mblk = m >> 7, mi = m & 127;
        int wm = mi >> 6, mb = (mi >> 4) & 3, hi = (mi >> 3) & 1, ra = mi & 7;
        int it = k >> 5, kin = k & 31, ks = kin >> 3, c7 = kin & 7, half = c7 >> 2, cq = c7 & 3;
        size_t idx = (((size_t)(mblk * KB24 + it) * 8 + (wm * 4 + mb)) * 4 + ks) * 32 + (ra * 4 + cq);
        g_xf[idx * 4 + half * 2 + hi] = v;
    }
    for (int j = i; j < NQKV * C_; j += stride) {
        int n = j / C_, k = j - n * C_;
        float v = f2tf32(wq[j]);
        int nblk = n >> 7, ni = n & 127;
        int wn = ni >> 5, nb = (ni >> 3) & 3, ra = ni & 7;
        int p = nb >> 1, pb = nb & 1;
        int it = k >> 5, kin = k & 31, ks = kin >> 3, c7 = kin & 7, half = c7 >> 2, cq = c7 & 3;
        size_t idx = (((size_t)(nblk * KB24 + it) * 8 + (wn * 2 + p)) * 4 + ks) * 32 + (ra * 4 + cq);
        g_wqf[idx * 4 + pb * 2 + half] = v;
    }
    for (int j = i; j < C_ * C_; j += stride) {
        int n = j / C_, k = j - n * C_;
        float v = f2tf32(wo[j]);
        int nblk = n >> 7, ni = n & 127;
        int wn = ni >> 5, nb = (ni >> 3) & 3, ra = ni & 7;
        int p = nb >> 1, pb = nb & 1;
        int it = k >> 5, kin = k & 31, ks = kin >> 3, c7 = kin & 7, half = c7 >> 2, cq = c7 & 3;
        size_t idx = (((size_t)(nblk * KB24 + it) * 8 + (wn * 2 + p)) * 4 + ks) * 32 + (ra * 4 + cq);
        g_wof[idx * 4 + pb * 2 + half] = v;
    }
}

// ---------------- TF32 MMA GEMM: 4 warps, 64x64 warp tiles (R15, measured best) -
#define EPAD 132
#define GEMM_SMEM (3 * 2048 * 16)    // 98304 B

__global__ __launch_bounds__(128, 2) void gemm_tf32_kernel(
    const float4* __restrict__ Af, const float4* __restrict__ Bf,
    float* __restrict__ C, int KB, int N, int fuse_rope)
{
    extern __shared__ float4 sg4[];

    const int tid = threadIdx.x;
    const int warp = tid >> 5;           // 0..3
    const int lane = tid & 31;
    const int rA = lane >> 2;
    const int cq = lane & 3;
    const int warp_m = warp & 1;
    const int warp_n = warp >> 1;        // 0..1

    float acc[4][8][4];
#pragma unroll
    for (int a = 0; a < 4; a++)
#pragma unroll
        for (int b = 0; b < 8; b++)
#pragma unroll
            for (int c = 0; c < 4; c++) acc[a][b][c] = 0.f;

    auto issue = [&](int it, int st) {
        const float4* ga = Af + (size_t)(blockIdx.y * KB + it) * 1024;
        const float4* gb = Bf + (size_t)(blockIdx.x * KB + it) * 1024;
        float4* da = sg4 + st * 2048;
        float4* db = da + 1024;
#pragma unroll
        for (int l = 0; l < 8; l++) {
            int slot = l * 128 + tid;
            cp_async16(smem_u32(&da[slot]), &ga[slot]);
            cp_async16(smem_u32(&db[slot]), &gb[slot]);
        }
        cp_async_commit();
    };

    issue(0, 0);
    if (KB > 1) issue(1, 1);

    int st = 0, st2 = 2;
    for (int it = 0; it < KB; it++) {
        if (it + 1 < KB) cp_async_wait1(); else cp_async_wait0();
        __syncthreads();

        float4* As = sg4 + st * 2048;
        float4* Bs = As + 1024;
#pragma unroll
        for (int ks = 0; ks < 4; ks++) {
            float4 a4[4];
#pragma unroll
            for (int mb = 0; mb < 4; mb++)
                a4[mb] = As[((warp_m * 4 + mb) * 4 + ks) * 32 + lane];
            float4 b4[4];
#pragma unroll
            for (int g = 0; g < 4; g++)
                b4[g] = Bs[((warp_n * 4 + g) * 4 + ks) * 32 + lane];
#pragma unroll
            for (int mb = 0; mb < 4; mb++)
#pragma unroll
                for (int g = 0; g < 4; g++) {
                    mma_tf32(acc[mb][2 * g],     a4[mb].x, a4[mb].y, a4[mb].z, a4[mb].w, b4[g].x, b4[g].y);
                    mma_tf32(acc[mb][2 * g + 1], a4[mb].x, a4[mb].y, a4[mb].z, a4[mb].w, b4[g].z, b4[g].w);
                }
        }

        if (it + 2 < KB) issue(it + 2, st2);
        st = (st == 2) ? 0 : st + 1;
        st2 = (st2 == 2) ? 0 : st2 + 1;
    }

    const int m0 = blockIdx.y * 128;
    const int n0 = blockIdx.x * 128;

    if (!fuse_rope) {
#pragma unroll
        for (int mb = 0; mb < 4; mb++) {
            int row = m0 + warp_m * 64 + mb * 16 + rA;
#pragma unroll
            for (int nbb = 0; nbb < 8; nbb++) {
                int col = n0 + warp_n * 64 + nbb * 8 + 2 * cq;
                *(float2*)&C[(size_t)row * N + col] =
                    make_float2(acc[mb][nbb][0], acc[mb][nbb][1]);
                *(float2*)&C[(size_t)(row + 8) * N + col] =
                    make_float2(acc[mb][nbb][2], acc[mb][nbb][3]);
            }
        }
        return;
    }

    // --- fused RoPE + fragment scatter epilogue (QKV GEMM only) ---
    __syncthreads();
    float* ep = (float*)sg4;             // overlay [128][132]
#pragma unroll
    for (int mb = 0; mb < 4; mb++) {
        int row = warp_m * 64 + mb * 16 + rA;
#pragma unroll
        for (int nbb = 0; nbb < 8; nbb++) {
            int col = warp_n * 64 + nbb * 8 + 2 * cq;
            *(float2*)&ep[row * EPAD + col] = make_float2(acc[mb][nbb][0], acc[mb][nbb][1]);
            *(float2*)&ep[(row + 8) * EPAD + col] = make_float2(acc[mb][nbb][2], acc[mb][nbb][3]);
        }
    }
    __syncthreads();

    const int sel = n0 / C_;
    const int cbase = n0 % C_;

#pragma unroll 4
    for (int e = 0; e < 128; e++) {
        int elem = e * 128 + tid;
        int r = elem >> 7, c = elem & 127;
        float val = ep[r * EPAD + c];

        int cc = cbase + c;
        int h = cc >> 6, d = cc & 63;
        int m = m0 + r;
        int b = m >> 11, t = m & (T_ - 1);

        if (sel < 2 && d < RD_) {
            int j = (d < 8) ? d : d - 8;
            float freq = __powf(10000.0f, -(float)j / 8.0f);
            float ang = (float)t * freq;
            float cs = cosf(ang), sn = sinf(ang);
            float partner = ep[r * EPAD + ((d < 8) ? c + 8 : c - 8)];
            val = (d < 8) ? (val * cs - partner * sn) : (val * cs + partner * sn);
        }
        if (sel == 0) val *= 0.125f * 1.4426950408889634f;
        val = f2tf32(val);

        const int bh = b * NH_ + h;
        if (sel == 0) {
            int g = t >> 4, tl = t & 15;
            int hi = tl >> 3, ra = tl & 7;
            int kb = d >> 3, c7 = d & 7, reg = c7 >> 2, q4 = c7 & 3;
            size_t off = (((size_t)bh * 128 + g) * 8 + kb) * 128 + (ra * 4 + q4) * 4 + hi + 2 * reg;
            g_qf[off] = val;
        } else if (sel == 1) {
            int kt = t >> 6, tl = t & 63;
            int nb = tl >> 3, ra = tl & 7;
            int kb = d >> 3, c7 = d & 7, reg = c7 >> 2, q4 = c7 & 3;
            size_t off = ((size_t)bh * 32 + kt) * 4096
                       + ((nb * 4 + (kb >> 1)) * 32 + ra * 4 + q4) * 4 + (kb & 1) * 2 + reg;
            g_kf[off] = val;
        } else {
            int kt = t >> 6, tl = t & 63;
            int kb2 = tl >> 3, c7 = tl & 7, reg = c7 >> 2, q4 = c7 & 3;
            int nb2 = d >> 3, ra = d & 7;
            size_t off = ((size_t)bh * 32 + kt) * 4096
                       + ((kb2 * 4 + (nb2 >> 1)) * 32 + ra * 4 + q4) * 4 + (nb2 & 1) * 2 + reg;
            g_vf[off] = val;
        }
    }
}

// ---------------- Flash attention (R14 version: 8 warps x 16 rows) -------------
#define FLASH_SMEM (6 * 1024 * 16)   // 98304 B

__global__ __launch_bounds__(256, 2) void flash_kernel()
{
    extern __shared__ float4 smf[];

    const int tid = threadIdx.x;
    const int warp = tid >> 5;
    const int lane = tid & 31;
    const int rA = lane >> 2;
    const int cq = lane & 3;

    const int qt = (int)gridDim.x - 1 - (int)blockIdx.x;
    const int bh = blockIdx.y;
    const int q0 = qt * 128;

    const int b = bh / NH_, h = bh % NH_;
    const int qrow = q0 + warp * 16 + rA;

    const float4* Qf = (const float4*)g_qf;
    float qa[8][4];
#pragma unroll
    for (int kb = 0; kb < 8; kb++) {
        float4 f = Qf[(((size_t)bh * 128 + 8 * qt + warp) * 8 + kb) * 32 + lane];
        qa[kb][0] = f.x; qa[kb][1] = f.y; qa[kb][2] = f.z; qa[kb][3] = f.w;
    }

    float o[8][4];
#pragma unroll
    for (int i = 0; i < 8; i++)
#pragma unroll
        for (int j = 0; j < 4; j++) o[i][j] = 0.f;
    float mA = -1e30f, mB = -1e30f, lA = 0.f, lB = 0.f;

    const float4* Kf = (const float4*)g_kf;
    const float4* Vf = (const float4*)g_vf;

    auto issue_tile = [&](int kt, int st) {
        const size_t tb = ((size_t)bh * 32 + kt) * 1024;
        float4* Ksb = smf + st * 1024;
        float4* Vsb = smf + 3072 + st * 1024;
#pragma unroll
        for (int l = 0; l < 4; l++) {
            int slot = l * 256 + tid;
            cp_async16(smem_u32(&Ksb[slot]), &Kf[tb + slot]);
            cp_async16(smem_u32(&Vsb[slot]), &Vf[tb + slot]);
        }
        cp_async_commit();
    };

    const int ktiles = 2 * qt + 2;
    issue_tile(0, 0);
    if (ktiles > 1) issue_tile(1, 1);

    const int srcA = (lane & ~3) | (cq >> 1);
    const int srcB = srcA + 2;
    const bool par = (cq & 1);

    int st = 0, st2 = 2;
    for (int kt = 0; kt < ktiles; kt++) {
        if (kt + 1 < ktiles) cp_async_wait1(); else cp_async_wait0();
        __syncthreads();

        float4* Ksf = smf + st * 1024;
        float4* Vsf = smf + 3072 + st * 1024;

        float s[8][4];
#pragma unroll
        for (int nb = 0; nb < 8; nb++)
#pragma unroll
            for (int j = 0; j < 4; j++) s[nb][j] = 0.f;
#pragma unroll
        for (int kbp = 0; kbp < 4; kbp++) {
#pragma unroll
            for (int nb = 0; nb < 8; nb++) {
                float4 f = Ksf[(nb * 4 + kbp) * 32 + lane];
                mma_tf32(s[nb], qa[2 * kbp][0], qa[2 * kbp][1], qa[2 * kbp][2], qa[2 * kbp][3], f.x, f.y);
                mma_tf32(s[nb], qa[2 * kbp + 1][0], qa[2 * kbp + 1][1], qa[2 * kbp + 1][2], qa[2 * kbp + 1][3], f.z, f.w);
            }
        }

        const int k0 = kt * 64;
        if (k0 + 63 > qrow) {
#pragma unroll
            for (int nb = 0; nb < 8; nb++) {
                int col = k0 + 8 * nb + 2 * cq;
                if (col > qrow)     s[nb][0] = -1e30f;
                if (col + 1 > qrow) s[nb][1] = -1e30f;
                if (col > qrow + 8)     s[nb][2] = -1e30f;
                if (col + 1 > qrow + 8) s[nb][3] = -1e30f;
            }
        }

        float rmaxA = -1e30f, rmaxB = -1e30f;
#pragma unroll
        for (int nb = 0; nb < 8; nb++) {
            rmaxA = fmaxf(rmaxA, fmaxf(s[nb][0], s[nb][1]));
            rmaxB = fmaxf(rmaxB, fmaxf(s[nb][2], s[nb][3]));
        }
        rmaxA = fmaxf(rmaxA, __shfl_xor_sync(0xffffffffu, rmaxA, 1));
        rmaxA = fmaxf(rmaxA, __shfl_xor_sync(0xffffffffu, rmaxA, 2));
        rmaxB = fmaxf(rmaxB, __shfl_xor_sync(0xffffffffu, rmaxB, 1));
        rmaxB = fmaxf(rmaxB, __shfl_xor_sync(0xffffffffu, rmaxB, 2));

        float mnA = fmaxf(mA, rmaxA), mnB = fmaxf(mB, rmaxB);
        float alA = exp2f(mA - mnA), alB = exp2f(mB - mnB);
        mA = mnA; mB = mnB;

        float sumA = 0.f, sumB = 0.f;
#pragma unroll
        for (int nb = 0; nb < 8; nb++) {
            s[nb][0] = exp2f(s[nb][0] - mA); sumA += s[nb][0];
            s[nb][1] = exp2f(s[nb][1] - mA); sumA += s[nb][1];
            s[nb][2] = exp2f(s[nb][2] - mB); sumB += s[nb][2];
            s[nb][3] = exp2f(s[nb][3] - mB); sumB += s[nb][3];
        }
        sumA += __shfl_xor_sync(0xffffffffu, sumA, 1);
        sumA += __shfl_xor_sync(0xffffffffu, sumA, 2);
        sumB += __shfl_xor_sync(0xffffffffu, sumB, 1);
        sumB += __shfl_xor_sync(0xffffffffu, sumB, 2);
        lA = lA * alA + sumA;
        lB = lB * alB + sumB;

#pragma unroll
        for (int nb = 0; nb < 8; nb++) {
            o[nb][0] *= alA; o[nb][1] *= alA;
            o[nb][2] *= alB; o[nb][3] *= alB;
        }

#pragma unroll
        for (int nb = 0; nb < 8; nb++)
#pragma unroll
            for (int j = 0; j < 4; j++) s[nb][j] = f2tf32(s[nb][j]);

#pragma unroll
        for (int kb2 = 0; kb2 < 8; kb2++) {
            float t0, t1;
            t0 = __shfl_sync(0xffffffffu, s[kb2][0], srcA);
            t1 = __shfl_sync(0xffffffffu, s[kb2][1], srcA);
            float pa0 = par ? t1 : t0;
            t0 = __shfl_sync(0xffffffffu, s[kb2][0], srcB);
            t1 = __shfl_sync(0xffffffffu, s[kb2][1], srcB);
            float pa2 = par ? t1 : t0;
            t0 = __shfl_sync(0xffffffffu, s[kb2][2], srcA);
            t1 = __shfl_sync(0xffffffffu, s[kb2][3], srcA);
            float pa1 = par ? t1 : t0;
            t0 = __shfl_sync(0xffffffffu, s[kb2][2], srcB);
            t1 = __shfl_sync(0xffffffffu, s[kb2][3], srcB);
            float pa3 = par ? t1 : t0;

#pragma unroll
            for (int nb2p = 0; nb2p < 4; nb2p++) {
                float4 f = Vsf[(kb2 * 4 + nb2p) * 32 + lane];
                mma_tf32(o[2 * nb2p],     pa0, pa1, pa2, pa3, f.x, f.y);
                mma_tf32(o[2 * nb2p + 1], pa0, pa1, pa2, pa3, f.z, f.w);
            }
        }

        if (kt + 2 < ktiles) issue_tile(kt + 2, st2);
        st = (st == 2) ? 0 : st + 1;
        st2 = (st2 == 2) ? 0 : st2 + 1;
    }

    // epilogue: normalize, tf32-round, C->A layout shuffle, store A-fragment order
    float invA = 1.f / lA, invB = 1.f / lB;
    float4* Of4 = (float4*)g_of;
#pragma unroll
    for (int nb2 = 0; nb2 < 8; nb2++) {
        float s0 = f2tf32(o[nb2][0] * invA);
        float s1 = f2tf32(o[nb2][1] * invA);
        float s2 = f2tf32(o[nb2][2] * invB);
        float s3 = f2tf32(o[nb2][3] * invB);

        float t0, t1;
        t0 = __shfl_sync(0xffffffffu, s0, srcA);
        t1 = __shfl_sync(0xffffffffu, s1, srcA);
        float pa0 = par ? t1 : t0;
        t0 = __shfl_sync(0xffffffffu, s0, srcB);
        t1 = __shfl_sync(0xffffffffu, s1, srcB);
        float pa2 = par ? t1 : t0;
        t0 = __shfl_sync(0xffffffffu, s2, srcA);
        t1 = __shfl_sync(0xffffffffu, s3, srcA);
        float pa1 = par ? t1 : t0;
        t0 = __shfl_sync(0xffffffffu, s2, srcB);
        t1 = __shfl_sync(0xffffffffu, s3, srcB);
        float pa3 = par ? t1 : t0;

        int itl = nb2 >> 2, ks = nb2 & 3;
        size_t idx = (((size_t)((b * 16 + qt) * KB24 + (2 * h + itl)) * 8 + warp) * 4 + ks) * 32 + lane;
        Of4[idx] = make_float4(pa0, pa1, pa2, pa3);
    }
}

// ---------------- launch ------------------------------------------------------
extern "C" void kernel_launch(void* const* d_in, const int* in_sizes, int n_in,
                              void* d_out, int out_size)
{
    const float* x     = (const float*)d_in[0];
    const float* w_qkv = (const float*)d_in[1];
    const float* w_out = (const float*)d_in[2];
    float* out = (float*)d_out;

    float *xf_p, *of_p, *wqf_p, *wof_p;
    cudaGetSymbolAddress((void**)&xf_p, g_xf);
    cudaGetSymbolAddress((void**)&of_p, g_of);
    cudaGetSymbolAddress((void**)&wqf_p, g_wqf);
    cudaGetSymbolAddress((void**)&wof_p, g_wof);

    // 0) round + fragment-reorder inputs
    prep_kernel<<<2048, 256>>>(x, w_qkv, w_out);

    cudaFuncSetAttribute(gemm_tf32_kernel, cudaFuncAttributeMaxDynamicSharedMemorySize, GEMM_SMEM);
    cudaFuncSetAttribute(flash_kernel, cudaFuncAttributeMaxDynamicSharedMemorySize, FLASH_SMEM);

    // 1) QKV GEMM with fused RoPE + fragment scatter
    {
        dim3 grid(NQKV / 128, M_ / 128);
        gemm_tf32_kernel<<<grid, 128, GEMM_SMEM>>>(
            (const float4*)xf_p, (const float4*)wqf_p, nullptr, KB24, NQKV, 1);
    }

    // 2) flash attention (writes g_of in A-fragment order)
    {
        dim3 grid(T_ / 128, B_ * NH_);
        flash_kernel<<<grid, 256, FLASH_SMEM>>>();
    }

    // 3) out projection (plain epilogue, row-major final output)
    {
        dim3 grid(C_ / 128, M_ / 128);
        gemm_tf32_kernel<<<grid, 128, GEMM_SMEM>>>(
            (const float4*)of_p, (const float4*)wof_p, out, KB24, C_, 0);
    }
}

// round 17
// speedup vs baseline: 1.1782x; 1.1459x over previous
#include <cuda_runtime.h>
#include <cuda_bf16.h>
#include <cstdint>
#include <math.h>

#define B_  4
#define T_  2048
#define C_  768
#define NH_ 12
#define HD_ 64
#define RD_ 16
#define M_  (B_ * T_)          // 8192
#define NQKV (3 * C_)          // 2304
#define KB24 24                // 768 / 32

// ---------------- scratch ----------------------------------------------------
__device__ float g_qf[B_ * NH_ * T_ * HD_];      // Q frag order, tf32, scale*log2e folded
__device__ float g_kf[B_ * NH_ * T_ * HD_];      // K frag order, tf32
__device__ float g_vf[B_ * NH_ * T_ * HD_];      // V frag order, tf32
__device__ float g_of[M_ * C_];                  // attn out, A-fragment order, tf32
__device__ float g_xf[M_ * C_];                  // x, A-fragment order, tf32
__device__ float g_wqf[NQKV * C_];               // w_qkv, B-fragment order, tf32
__device__ float g_wof[C_ * C_];                 // w_out, B-fragment order, tf32

// ---------------- helpers -----------------------------------------------------
__device__ __forceinline__ float f2tf32(float x) {
    unsigned u;
    asm("cvt.rna.tf32.f32 %0, %1;" : "=r"(u) : "f"(x));
    return __uint_as_float(u);
}

__device__ __forceinline__ void mma_tf32(float* c,
    float a0, float a1, float a2, float a3, float b0, float b1)
{
    asm volatile(
        "mma.sync.aligned.m16n8k8.row.col.f32.tf32.tf32.f32 "
        "{%0,%1,%2,%3}, {%4,%5,%6,%7}, {%8,%9}, {%0,%1,%2,%3};"
        : "+f"(c[0]), "+f"(c[1]), "+f"(c[2]), "+f"(c[3])
        : "r"(__float_as_uint(a0)), "r"(__float_as_uint(a1)),
          "r"(__float_as_uint(a2)), "r"(__float_as_uint(a3)),
          "r"(__float_as_uint(b0)), "r"(__float_as_uint(b1)));
}

__device__ __forceinline__ void cp_async16(unsigned int smem_addr, const void* gptr) {
    asm volatile("cp.async.cg.shared.global [%0], [%1], 16;\n"
                 :: "r"(smem_addr), "l"(gptr));
}
__device__ __forceinline__ void cp_async_commit() {
    asm volatile("cp.async.commit_group;\n" ::: "memory");
}
__device__ __forceinline__ void cp_async_wait0() {
    asm volatile("cp.async.wait_group 0;\n" ::: "memory");
}
__device__ __forceinline__ void cp_async_wait1() {
    asm volatile("cp.async.wait_group 1;\n" ::: "memory");
}
__device__ __forceinline__ unsigned int smem_u32(const void* p) {
    return (unsigned int)__cvta_generic_to_shared(p);
}

// ---------------- prep: tf32-round + fragment reorder x / weights ---------------
__global__ __launch_bounds__(256) void prep_kernel(
    const float* __restrict__ x, const float* __restrict__ wq, const float* __restrict__ wo)
{
    int i = blockIdx.x * 256 + threadIdx.x;
    int stride = gridDim.x * 256;

    for (int j = i; j < M_ * C_; j += stride) {
        int m = j / C_, k = j - m * C_;
        float v = f2tf32(x[j]);
        int mblk = m >> 7, mi = m & 127;
        int wm = mi >> 6, mb = (mi >> 4) & 3, hi = (mi >> 3) & 1, ra = mi & 7;
        int it = k >> 5, kin = k & 31, ks = kin >> 3, c7 = kin & 7, half = c7 >> 2, cq = c7 & 3;
        size_t idx = (((size_t)(mblk * KB24 + it) * 8 + (wm * 4 + mb)) * 4 + ks) * 32 + (ra * 4 + cq);
        g_xf[idx * 4 + half * 2 + hi] = v;
    }
    for (int j = i; j < NQKV * C_; j += stride) {
        int n = j / C_, k = j - n * C_;
        float v = f2tf32(wq[j]);
        int nblk = n >> 7, ni = n & 127;
        int wn = ni >> 5, nb = (ni >> 3) & 3, ra = ni & 7;
        int p = nb >> 1, pb = nb & 1;
        int it = k >> 5, kin = k & 31, ks = kin >> 3, c7 = kin & 7, half = c7 >> 2, cq = c7 & 3;
        size_t idx = (((size_t)(nblk * KB24 + it) * 8 + (wn * 2 + p)) * 4 + ks) * 32 + (ra * 4 + cq);
        g_wqf[idx * 4 + pb * 2 + half] = v;
    }
    for (int j = i; j < C_ * C_; j += stride) {
        int n = j / C_, k = j - n * C_;
        float v = f2tf32(wo[j]);
        int nblk = n >> 7, ni = n & 127;
        int wn = ni >> 5, nb = (ni >> 3) & 3, ra = ni & 7;
        int p = nb >> 1, pb = nb & 1;
        int it = k >> 5, kin = k & 31, ks = kin >> 3, c7 = kin & 7, half = c7 >> 2, cq = c7 & 3;
        size_t idx = (((size_t)(nblk * KB24 + it) * 8 + (wn * 2 + p)) * 4 + ks) * 32 + (ra * 4 + cq);
        g_wof[idx * 4 + pb * 2 + half] = v;
    }
}

// ---------------- QKV GEMM (R14: 8 warps, 64x32 warp tiles, fused RoPE) --------
#define EPAD 132
#define GEMM_SMEM (3 * 2048 * 16)    // 98304 B

__global__ __launch_bounds__(256, 2) void gemm_qkv_kernel(
    const float4* __restrict__ Af, const float4* __restrict__ Bf, int KB)
{
    extern __shared__ float4 sg4[];

    const int tid = threadIdx.x;
    const int warp = tid >> 5;
    const int lane = tid & 31;
    const int rA = lane >> 2;
    const int cq = lane & 3;
    const int warp_m = warp & 1;
    const int warp_n = warp >> 1;

    float acc[4][4][4];
#pragma unroll
    for (int a = 0; a < 4; a++)
#pragma unroll
        for (int b = 0; b < 4; b++)
#pragma unroll
            for (int c = 0; c < 4; c++) acc[a][b][c] = 0.f;

    auto issue = [&](int it, int st) {
        const float4* ga = Af + (size_t)(blockIdx.y * KB + it) * 1024;
        const float4* gb = Bf + (size_t)(blockIdx.x * KB + it) * 1024;
        float4* da = sg4 + st * 2048;
        float4* db = da + 1024;
#pragma unroll
        for (int l = 0; l < 4; l++) {
            int slot = l * 256 + tid;
            cp_async16(smem_u32(&da[slot]), &ga[slot]);
            cp_async16(smem_u32(&db[slot]), &gb[slot]);
        }
        cp_async_commit();
    };

    issue(0, 0);
    if (KB > 1) issue(1, 1);

    int st = 0, st2 = 2;
    for (int it = 0; it < KB; it++) {
        if (it + 1 < KB) cp_async_wait1(); else cp_async_wait0();
        __syncthreads();

        float4* As = sg4 + st * 2048;
        float4* Bs = As + 1024;
#pragma unroll
        for (int ks = 0; ks < 4; ks++) {
            float4 a4[4];
#pragma unroll
            for (int mb = 0; mb < 4; mb++)
                a4[mb] = As[((warp_m * 4 + mb) * 4 + ks) * 32 + lane];
            float4 b4[2];
#pragma unroll
            for (int p = 0; p < 2; p++)
                b4[p] = Bs[((warp_n * 2 + p) * 4 + ks) * 32 + lane];
#pragma unroll
            for (int mb = 0; mb < 4; mb++) {
                mma_tf32(acc[mb][0], a4[mb].x, a4[mb].y, a4[mb].z, a4[mb].w, b4[0].x, b4[0].y);
                mma_tf32(acc[mb][1], a4[mb].x, a4[mb].y, a4[mb].z, a4[mb].w, b4[0].z, b4[0].w);
                mma_tf32(acc[mb][2], a4[mb].x, a4[mb].y, a4[mb].z, a4[mb].w, b4[1].x, b4[1].y);
                mma_tf32(acc[mb][3], a4[mb].x, a4[mb].y, a4[mb].z, a4[mb].w, b4[1].z, b4[1].w);
            }
        }

        if (it + 2 < KB) issue(it + 2, st2);
        st = (st == 2) ? 0 : st + 1;
        st2 = (st2 == 2) ? 0 : st2 + 1;
    }

    const int m0 = blockIdx.y * 128;
    const int n0 = blockIdx.x * 128;

    // fused RoPE + fragment scatter epilogue
    __syncthreads();
    float* ep = (float*)sg4;             // overlay [128][132]
#pragma unroll
    for (int mb = 0; mb < 4; mb++) {
        int row = warp_m * 64 + mb * 16 + rA;
#pragma unroll
        for (int nb = 0; nb < 4; nb++) {
            int col = warp_n * 32 + nb * 8 + 2 * cq;
            *(float2*)&ep[row * EPAD + col] = make_float2(acc[mb][nb][0], acc[mb][nb][1]);
            *(float2*)&ep[(row + 8) * EPAD + col] = make_float2(acc[mb][nb][2], acc[mb][nb][3]);
        }
    }
    __syncthreads();

    const int sel = n0 / C_;
    const int cbase = n0 % C_;

#pragma unroll 4
    for (int e = 0; e < 64; e++) {
        int elem = e * 256 + tid;
        int r = elem >> 7, c = elem & 127;
        float val = ep[r * EPAD + c];

        int cc = cbase + c;
        int h = cc >> 6, d = cc & 63;
        int m = m0 + r;
        int b = m >> 11, t = m & (T_ - 1);

        if (sel < 2 && d < RD_) {
            int j = (d < 8) ? d : d - 8;
            float freq = __powf(10000.0f, -(float)j / 8.0f);
            float ang = (float)t * freq;
            float cs = cosf(ang), sn = sinf(ang);
            float partner = ep[r * EPAD + ((d < 8) ? c + 8 : c - 8)];
            val = (d < 8) ? (val * cs - partner * sn) : (val * cs + partner * sn);
        }
        if (sel == 0) val *= 0.125f * 1.4426950408889634f;
        val = f2tf32(val);

        const int bh = b * NH_ + h;
        if (sel == 0) {
            int g = t >> 4, tl = t & 15;
            int hi = tl >> 3, ra = tl & 7;
            int kb = d >> 3, c7 = d & 7, reg = c7 >> 2, q4 = c7 & 3;
            size_t off = (((size_t)bh * 128 + g) * 8 + kb) * 128 + (ra * 4 + q4) * 4 + hi + 2 * reg;
            g_qf[off] = val;
        } else if (sel == 1) {
            int kt = t >> 6, tl = t & 63;
            int nb = tl >> 3, ra = tl & 7;
            int kb = d >> 3, c7 = d & 7, reg = c7 >> 2, q4 = c7 & 3;
            size_t off = ((size_t)bh * 32 + kt) * 4096
                       + ((nb * 4 + (kb >> 1)) * 32 + ra * 4 + q4) * 4 + (kb & 1) * 2 + reg;
            g_kf[off] = val;
        } else {
            int kt = t >> 6, tl = t & 63;
            int kb2 = tl >> 3, c7 = tl & 7, reg = c7 >> 2, q4 = c7 & 3;
            int nb2 = d >> 3, ra = d & 7;
            size_t off = ((size_t)bh * 32 + kt) * 4096
                       + ((kb2 * 4 + (nb2 >> 1)) * 32 + ra * 4 + q4) * 4 + (nb2 & 1) * 2 + reg;
            g_vf[off] = val;
        }
    }
}

// ---------------- Out-proj GEMM (R15: 4 warps, 64x64 warp tiles, plain) --------
__global__ __launch_bounds__(128, 2) void gemm_out_kernel(
    const float4* __restrict__ Af, const float4* __restrict__ Bf,
    float* __restrict__ C, int KB, int N)
{
    extern __shared__ float4 sg4[];

    const int tid = threadIdx.x;
    const int warp = tid >> 5;           // 0..3
    const int lane = tid & 31;
    const int rA = lane >> 2;
    const int cq = lane & 3;
    const int warp_m = warp & 1;
    const int warp_n = warp >> 1;        // 0..1

    float acc[4][8][4];
#pragma unroll
    for (int a = 0; a < 4; a++)
#pragma unroll
        for (int b = 0; b < 8; b++)
#pragma unroll
            for (int c = 0; c < 4; c++) acc[a][b][c] = 0.f;

    auto issue = [&](int it, int st) {
        const float4* ga = Af + (size_t)(blockIdx.y * KB + it) * 1024;
        const float4* gb = Bf + (size_t)(blockIdx.x * KB + it) * 1024;
        float4* da = sg4 + st * 2048;
        float4* db = da + 1024;
#pragma unroll
        for (int l = 0; l < 8; l++) {
            int slot = l * 128 + tid;
            cp_async16(smem_u32(&da[slot]), &ga[slot]);
            cp_async16(smem_u32(&db[slot]), &gb[slot]);
        }
        cp_async_commit();
    };

    issue(0, 0);
    if (KB > 1) issue(1, 1);

    int st = 0, st2 = 2;
    for (int it = 0; it < KB; it++) {
        if (it + 1 < KB) cp_async_wait1(); else cp_async_wait0();
        __syncthreads();

        float4* As = sg4 + st * 2048;
        float4* Bs = As + 1024;
#pragma unroll
        for (int ks = 0; ks < 4; ks++) {
            float4 a4[4];
#pragma unroll
            for (int mb = 0; mb < 4; mb++)
                a4[mb] = As[((warp_m * 4 + mb) * 4 + ks) * 32 + lane];
            float4 b4[4];
#pragma unroll
            for (int g = 0; g < 4; g++)
                b4[g] = Bs[((warp_n * 4 + g) * 4 + ks) * 32 + lane];
#pragma unroll
            for (int mb = 0; mb < 4; mb++)
#pragma unroll
                for (int g = 0; g < 4; g++) {
                    mma_tf32(acc[mb][2 * g],     a4[mb].x, a4[mb].y, a4[mb].z, a4[mb].w, b4[g].x, b4[g].y);
                    mma_tf32(acc[mb][2 * g + 1], a4[mb].x, a4[mb].y, a4[mb].z, a4[mb].w, b4[g].z, b4[g].w);
                }
        }

        if (it + 2 < KB) issue(it + 2, st2);
        st = (st == 2) ? 0 : st + 1;
        st2 = (st2 == 2) ? 0 : st2 + 1;
    }

    const int m0 = blockIdx.y * 128;
    const int n0 = blockIdx.x * 128;
#pragma unroll
    for (int mb = 0; mb < 4; mb++) {
        int row = m0 + warp_m * 64 + mb * 16 + rA;
#pragma unroll
        for (int nbb = 0; nbb < 8; nbb++) {
            int col = n0 + warp_n * 64 + nbb * 8 + 2 * cq;
            *(float2*)&C[(size_t)row * N + col] =
                make_float2(acc[mb][nbb][0], acc[mb][nbb][1]);
            *(float2*)&C[(size_t)(row + 8) * N + col] =
                make_float2(acc[mb][nbb][2], acc[mb][nbb][3]);
        }
    }
}

// ---------------- Flash attention (R14: 8 warps x 16 rows) ---------------------
#define FLASH_SMEM (6 * 1024 * 16)   // 98304 B

__global__ __launch_bounds__(256, 2) void flash_kernel()
{
    extern __shared__ float4 smf[];

    const int tid = threadIdx.x;
    const int warp = tid >> 5;
    const int lane = tid & 31;
    const int rA = lane >> 2;
    const int cq = lane & 3;

    const int qt = (int)gridDim.x - 1 - (int)blockIdx.x;
    const int bh = blockIdx.y;
    const int q0 = qt * 128;

    const int b = bh / NH_, h = bh % NH_;
    const int qrow = q0 + warp * 16 + rA;

    const float4* Qf = (const float4*)g_qf;
    float qa[8][4];
#pragma unroll
    for (int kb = 0; kb < 8; kb++) {
        float4 f = Qf[(((size_t)bh * 128 + 8 * qt + warp) * 8 + kb) * 32 + lane];
        qa[kb][0] = f.x; qa[kb][1] = f.y; qa[kb][2] = f.z; qa[kb][3] = f.w;
    }

    float o[8][4];
#pragma unroll
    for (int i = 0; i < 8; i++)
#pragma unroll
        for (int j = 0; j < 4; j++) o[i][j] = 0.f;
    float mA = -1e30f, mB = -1e30f, lA = 0.f, lB = 0.f;

    const float4* Kf = (const float4*)g_kf;
    const float4* Vf = (const float4*)g_vf;

    auto issue_tile = [&](int kt, int st) {
        const size_t tb = ((size_t)bh * 32 + kt) * 1024;
        float4* Ksb = smf + st * 1024;
        float4* Vsb = smf + 3072 + st * 1024;
#pragma unroll
        for (int l = 0; l < 4; l++) {
            int slot = l * 256 + tid;
            cp_async16(smem_u32(&Ksb[slot]), &Kf[tb + slot]);
            cp_async16(smem_u32(&Vsb[slot]), &Vf[tb + slot]);
        }
        cp_async_commit();
    };

    const int ktiles = 2 * qt + 2;
    issue_tile(0, 0);
    if (ktiles > 1) issue_tile(1, 1);

    const int srcA = (lane & ~3) | (cq >> 1);
    const int srcB = srcA + 2;
    const bool par = (cq & 1);

    int st = 0, st2 = 2;
    for (int kt = 0; kt < ktiles; kt++) {
        if (kt + 1 < ktiles) cp_async_wait1(); else cp_async_wait0();
        __syncthreads();

        float4* Ksf = smf + st * 1024;
        float4* Vsf = smf + 3072 + st * 1024;

        float s[8][4];
#pragma unroll
        for (int nb = 0; nb < 8; nb++)
#pragma unroll
            for (int j = 0; j < 4; j++) s[nb][j] = 0.f;
#pragma unroll
        for (int kbp = 0; kbp < 4; kbp++) {
#pragma unroll
            for (int nb = 0; nb < 8; nb++) {
                float4 f = Ksf[(nb * 4 + kbp) * 32 + lane];
                mma_tf32(s[nb], qa[2 * kbp][0], qa[2 * kbp][1], qa[2 * kbp][2], qa[2 * kbp][3], f.x, f.y);
                mma_tf32(s[nb], qa[2 * kbp + 1][0], qa[2 * kbp + 1][1], qa[2 * kbp + 1][2], qa[2 * kbp + 1][3], f.z, f.w);
            }
        }

        const int k0 = kt * 64;
        if (k0 + 63 > qrow) {
#pragma unroll
            for (int nb = 0; nb < 8; nb++) {
                int col = k0 + 8 * nb + 2 * cq;
                if (col > qrow)     s[nb][0] = -1e30f;
                if (col + 1 > qrow) s[nb][1] = -1e30f;
                if (col > qrow + 8)     s[nb][2] = -1e30f;
                if (col + 1 > qrow + 8) s[nb][3] = -1e30f;
            }
        }

        float rmaxA = -1e30f, rmaxB = -1e30f;
#pragma unroll
        for (int nb = 0; nb < 8; nb++) {
            rmaxA = fmaxf(rmaxA, fmaxf(s[nb][0], s[nb][1]));
            rmaxB = fmaxf(rmaxB, fmaxf(s[nb][2], s[nb][3]));
        }
        rmaxA = fmaxf(rmaxA, __shfl_xor_sync(0xffffffffu, rmaxA, 1));
        rmaxA = fmaxf(rmaxA, __shfl_xor_sync(0xffffffffu, rmaxA, 2));
        rmaxB = fmaxf(rmaxB, __shfl_xor_sync(0xffffffffu, rmaxB, 1));
        rmaxB = fmaxf(rmaxB, __shfl_xor_sync(0xffffffffu, rmaxB, 2));

        float mnA = fmaxf(mA, rmaxA), mnB = fmaxf(mB, rmaxB);
        float alA = exp2f(mA - mnA), alB = exp2f(mB - mnB);
        mA = mnA; mB = mnB;

        float sumA = 0.f, sumB = 0.f;
#pragma unroll
        for (int nb = 0; nb < 8; nb++) {
            s[nb][0] = exp2f(s[nb][0] - mA); sumA += s[nb][0];
            s[nb][1] = exp2f(s[nb][1] - mA); sumA += s[nb][1];
            s[nb][2] = exp2f(s[nb][2] - mB); sumB += s[nb][2];
            s[nb][3] = exp2f(s[nb][3] - mB); sumB += s[nb][3];
        }
        sumA += __shfl_xor_sync(0xffffffffu, sumA, 1);
        sumA += __shfl_xor_sync(0xffffffffu, sumA, 2);
        sumB += __shfl_xor_sync(0xffffffffu, sumB, 1);
        sumB += __shfl_xor_sync(0xffffffffu, sumB, 2);
        lA = lA * alA + sumA;
        lB = lB * alB + sumB;

#pragma unroll
        for (int nb = 0; nb < 8; nb++) {
            o[nb][0] *= alA; o[nb][1] *= alA;
            o[nb][2] *= alB; o[nb][3] *= alB;
        }

#pragma unroll
        for (int nb = 0; nb < 8; nb++)
#pragma unroll
            for (int j = 0; j < 4; j++) s[nb][j] = f2tf32(s[nb][j]);

#pragma unroll
        for (int kb2 = 0; kb2 < 8; kb2++) {
            float t0, t1;
            t0 = __shfl_sync(0xffffffffu, s[kb2][0], srcA);
            t1 = __shfl_sync(0xffffffffu, s[kb2][1], srcA);
            float pa0 = par ? t1 : t0;
            t0 = __shfl_sync(0xffffffffu, s[kb2][0], srcB);
            t1 = __shfl_sync(0xffffffffu, s[kb2][1], srcB);
            float pa2 = par ? t1 : t0;
            t0 = __shfl_sync(0xffffffffu, s[kb2][2], srcA);
            t1 = __shfl_sync(0xffffffffu, s[kb2][3], srcA);
            float pa1 = par ? t1 : t0;
            t0 = __shfl_sync(0xffffffffu, s[kb2][2], srcB);
            t1 = __shfl_sync(0xffffffffu, s[kb2][3], srcB);
            float pa3 = par ? t1 : t0;

#pragma unroll
            for (int nb2p = 0; nb2p < 4; nb2p++) {
                float4 f = Vsf[(kb2 * 4 + nb2p) * 32 + lane];
                mma_tf32(o[2 * nb2p],     pa0, pa1, pa2, pa3, f.x, f.y);
                mma_tf32(o[2 * nb2p + 1], pa0, pa1, pa2, pa3, f.z, f.w);
            }
        }

        if (kt + 2 < ktiles) issue_tile(kt + 2, st2);
        st = (st == 2) ? 0 : st + 1;
        st2 = (st2 == 2) ? 0 : st2 + 1;
    }

    // epilogue: normalize, tf32-round, C->A layout shuffle, store A-fragment order
    float invA = 1.f / lA, invB = 1.f / lB;
    float4* Of4 = (float4*)g_of;
#pragma unroll
    for (int nb2 = 0; nb2 < 8; nb2++) {
        float s0 = f2tf32(o[nb2][0] * invA);
        float s1 = f2tf32(o[nb2][1] * invA);
        float s2 = f2tf32(o[nb2][2] * invB);
        float s3 = f2tf32(o[nb2][3] * invB);

        float t0, t1;
        t0 = __shfl_sync(0xffffffffu, s0, srcA);
        t1 = __shfl_sync(0xffffffffu, s1, srcA);
        float pa0 = par ? t1 : t0;
        t0 = __shfl_sync(0xffffffffu, s0, srcB);
        t1 = __shfl_sync(0xffffffffu, s1, srcB);
        float pa2 = par ? t1 : t0;
        t0 = __shfl_sync(0xffffffffu, s2, srcA);
        t1 = __shfl_sync(0xffffffffu, s3, srcA);
        float pa1 = par ? t1 : t0;
        t0 = __shfl_sync(0xffffffffu, s2, srcB);
        t1 = __shfl_sync(0xffffffffu, s3, srcB);
        float pa3 = par ? t1 : t0;

        int itl = nb2 >> 2, ks = nb2 & 3;
        size_t idx = (((size_t)((b * 16 + qt) * KB24 + (2 * h + itl)) * 8 + warp) * 4 + ks) * 32 + lane;
        Of4[idx] = make_float4(pa0, pa1, pa2, pa3);
    }
}

// ---------------- launch ------------------------------------------------------
extern "C" void kernel_launch(void* const* d_in, const int* in_sizes, int n_in,
                              void* d_out, int out_size)
{
    const float* x     = (const float*)d_in[0];
    const float* w_qkv = (const float*)d_in[1];
    const float* w_out = (const float*)d_in[2];
    float* out = (float*)d_out;

    float *xf_p, *of_p, *wqf_p, *wof_p;
    cudaGetSymbolAddress((void**)&xf_p, g_xf);
    cudaGetSymbolAddress((void**)&of_p, g_of);
    cudaGetSymbolAddress((void**)&wqf_p, g_wqf);
    cudaGetSymbolAddress((void**)&wof_p, g_wof);

    // 0) round + fragment-reorder inputs
    prep_kernel<<<2048, 256>>>(x, w_qkv, w_out);

    cudaFuncSetAttribute(gemm_qkv_kernel, cudaFuncAttributeMaxDynamicSharedMemorySize, GEMM_SMEM);
    cudaFuncSetAttribute(gemm_out_kernel, cudaFuncAttributeMaxDynamicSharedMemorySize, GEMM_SMEM);
    cudaFuncSetAttribute(flash_kernel, cudaFuncAttributeMaxDynamicSharedMemorySize, FLASH_SMEM);

    // 1) QKV GEMM with fused RoPE + fragment scatter (8 warps, R14 config)
    {
        dim3 grid(NQKV / 128, M_ / 128);
        gemm_qkv_kernel<<<grid, 256, GEMM_SMEM>>>(
            (const float4*)xf_p, (const float4*)wqf_p, KB24);
    }

    // 2) flash attention (R14 config, writes g_of in A-fragment order)
    {
        dim3 grid(T_ / 128, B_ * NH_);
        flash_kernel<<<grid, 256, FLASH_SMEM>>>();
    }

    // 3) out projection (4 warps, 64x64 tiles — measured fastest plain GEMM)
    {
        dim3 grid(C_ / 128, M_ / 128);
        gemm_out_kernel<<<grid, 128, GEMM_SMEM>>>(
            (const float4*)of_p, (const float4*)wof_p, out, KB24, C_);
    }
}